// round 1
// baseline (speedup 1.0000x reference)
#include <cuda_runtime.h>
#include <math.h>

// Problem constants
#define BATCH 64
#define L0 128
#define C0 16
#define KW 5
#define C1 128      // block1 output channels
#define L1 124
#define C2 1024     // block2 output channels
#define L2N 120
#define C3 8192     // block3 output channels
#define L3 116
#define AD 2

// k_back tiling
#define TT 4              // t3 tile per CTA
#define GPC 256           // g3 groups per CTA (== blockDim)
#define BSPLIT 2
#define BPC (BATCH / BSPLIT)   // 32 batches per CTA

// Scratch (device globals; no allocation)
__device__ float g_y2[(size_t)BATCH * L2N * C2];   // ~31.5 MB, L2-resident
__device__ float g_accum[BATCH * AD];

__global__ void k_zero() {
    g_accum[threadIdx.x] = 0.f;
}

// ---------------------------------------------------------------------------
// Kernel 1: per (b, t-half) compute y1 slice in smem, then y2 half -> global.
// grid (64, 2), block 256.
// ---------------------------------------------------------------------------
__global__ __launch_bounds__(256) void k_front(
    const float* __restrict__ state, const float* __restrict__ k1,
    const float* __restrict__ b1, const float* __restrict__ k2,
    const float* __restrict__ b2)
{
    __shared__ float s_y1[64 * C1];   // y1 rows [t0, t0+64)  (32 KB)
    const int b   = blockIdx.x;
    const int ty  = blockIdx.y;
    const int tid = threadIdx.x;
    const int t0  = ty * 60;
    const float* st = state + (size_t)b * L0 * C0;

    // ---- y1 rows t0..t0+63 (each thread: fixed c1, t strided by 2) ----
    {
        const int c1 = tid & (C1 - 1);
        const int g1 = c1 >> 3;
        float kr[KW];
        const float bb = b1[c1];
        #pragma unroll
        for (int k = 0; k < KW; k++) kr[k] = k1[k * C1 + c1];
        for (int i = (tid >> 7); i < 64; i += 2) {
            const int t = t0 + i;
            float z = bb;
            #pragma unroll
            for (int k = 0; k < KW; k++)
                z = fmaf(st[(t + k) * C0 + g1], kr[k], z);
            s_y1[i * C1 + c1] = fmaxf(z, 0.f);
        }
    }
    __syncthreads();

    // ---- y2 rows t0..t0+59 ----
    for (int q = 0; q < 4; q++) {
        const int c2 = tid + q * 256;
        const int g2 = c2 >> 3;
        float kr[KW];
        const float bb = b2[c2];
        #pragma unroll
        for (int k = 0; k < KW; k++) kr[k] = k2[k * C2 + c2];
        float* yout = g_y2 + ((size_t)b * L2N + t0) * C2 + c2;
        for (int i = 0; i < 60; i++) {
            float z = bb;
            #pragma unroll
            for (int k = 0; k < KW; k++)
                z = fmaf(s_y1[(i + k) * C1 + g2], kr[k], z);
            yout[(size_t)i * C2] = fmaxf(z, 0.f);
        }
    }
}

// ---------------------------------------------------------------------------
// Kernel 2: fused block3 + dense. Each thread owns one g3 (8 channels),
// registers hold k3/b3/W slices, loop over batches streaming y2.
// grid (L3/TT = 29, C2/GPC = 4, BSPLIT = 2), block 256.
// ---------------------------------------------------------------------------
__global__ __launch_bounds__(256, 1) void k_back(
    const float* __restrict__ k3, const float* __restrict__ b3,
    const float* __restrict__ W)
{
    __shared__ float s_acc[BPC * AD];
    const int tid = threadIdx.x;
    const int t30 = blockIdx.x * TT;
    const int g3  = blockIdx.y * GPC + tid;
    const int b0  = blockIdx.z * BPC;
    if (tid < BPC * AD) s_acc[tid] = 0.f;
    __syncthreads();

    const int c3b = g3 * 8;

    // Hoist weights into registers
    float kr[KW][8];
    #pragma unroll
    for (int k = 0; k < KW; k++) {
        float4 a  = *(const float4*)(k3 + k * C3 + c3b);
        float4 bq = *(const float4*)(k3 + k * C3 + c3b + 4);
        kr[k][0]=a.x;  kr[k][1]=a.y;  kr[k][2]=a.z;  kr[k][3]=a.w;
        kr[k][4]=bq.x; kr[k][5]=bq.y; kr[k][6]=bq.z; kr[k][7]=bq.w;
    }
    float br[8];
    {
        float4 a  = *(const float4*)(b3 + c3b);
        float4 bq = *(const float4*)(b3 + c3b + 4);
        br[0]=a.x;  br[1]=a.y;  br[2]=a.z;  br[3]=a.w;
        br[4]=bq.x; br[5]=bq.y; br[6]=bq.z; br[7]=bq.w;
    }
    float wr[TT][8][2];
    #pragma unroll
    for (int i = 0; i < TT; i++) {
        const float* wp = W + ((size_t)(t30 + i) * C3 + c3b) * AD;
        #pragma unroll
        for (int j = 0; j < 4; j++) {
            float4 a = *(const float4*)(wp + j * 4);
            wr[i][2*j][0]   = a.x; wr[i][2*j][1]   = a.y;
            wr[i][2*j+1][0] = a.z; wr[i][2*j+1][1] = a.w;
        }
    }

    const int lane = tid & 31;
    for (int bb = 0; bb < BPC; bb++) {
        const int b = b0 + bb;
        const float* yp = g_y2 + ((size_t)b * L2N + t30) * C2 + g3;
        float yv[TT + 4];
        #pragma unroll
        for (int t = 0; t < TT + 4; t++) yv[t] = yp[(size_t)t * C2];

        float a0 = 0.f, a1 = 0.f;
        #pragma unroll
        for (int i = 0; i < TT; i++) {
            #pragma unroll
            for (int f = 0; f < 8; f++) {
                float z = br[f];
                #pragma unroll
                for (int k = 0; k < KW; k++)
                    z = fmaf(yv[i + k], kr[k][f], z);
                const float v = fmaxf(z, 0.f);
                a0 = fmaf(v, wr[i][f][0], a0);
                a1 = fmaf(v, wr[i][f][1], a1);
            }
        }
        // warp reduce the two partials
        #pragma unroll
        for (int off = 16; off; off >>= 1) {
            a0 += __shfl_xor_sync(0xffffffffu, a0, off);
            a1 += __shfl_xor_sync(0xffffffffu, a1, off);
        }
        if (lane == 0) {
            atomicAdd(&s_acc[bb * 2],     a0);
            atomicAdd(&s_acc[bb * 2 + 1], a1);
        }
    }
    __syncthreads();
    if (tid < BPC * AD)
        atomicAdd(&g_accum[b0 * AD + tid], s_acc[tid]);
}

// ---------------------------------------------------------------------------
// Kernel 3: bias + tanh
// ---------------------------------------------------------------------------
__global__ void k_out(const float* __restrict__ bd, float* __restrict__ out) {
    const int i = threadIdx.x;   // 128
    out[i] = tanhf(g_accum[i] + bd[i & 1]);
}

extern "C" void kernel_launch(void* const* d_in, const int* in_sizes, int n_in,
                              void* d_out, int out_size) {
    (void)in_sizes; (void)n_in; (void)out_size;
    const float* state = (const float*)d_in[0];
    const float* k1    = (const float*)d_in[1];
    const float* b1    = (const float*)d_in[2];
    const float* k2    = (const float*)d_in[3];
    const float* b2    = (const float*)d_in[4];
    const float* k3    = (const float*)d_in[5];
    const float* b3    = (const float*)d_in[6];
    const float* W     = (const float*)d_in[7];
    const float* bd    = (const float*)d_in[8];
    float* out = (float*)d_out;

    k_zero <<<1, 128>>>();
    k_front<<<dim3(BATCH, 2), 256>>>(state, k1, b1, k2, b2);
    k_back <<<dim3(L3 / TT, C2 / GPC, BSPLIT), 256>>>(k3, b3, W);
    k_out  <<<1, 128>>>(bd, out);
}

// round 2
// speedup vs baseline: 1.2556x; 1.2556x over previous
#include <cuda_runtime.h>
#include <math.h>

typedef unsigned long long ull;

// Problem constants
#define BATCH 64
#define L0 128
#define C0 16
#define KW 5
#define C1 128
#define L1 124
#define C2 1024
#define L2N 120
#define C3 8192
#define L3 116
#define AD 2

// k_back tiling
#define TT 4                  // t outputs per tile
#define NTBLK (L3 / TT)       // 29
#define NGBLK (C2 / 256)      // 4 (256 groups per CTA = blockDim)
#define NTG (NTBLK * NGBLK)   // 116
#define BPC 8                 // batches per item
#define NBCH (BATCH / BPC)    // 8
#define NITEMS (NTG * NBCH)   // 928
#define GRID_BACK 148

// Scratch (device globals; no allocation)
__device__ float g_y2[(size_t)BATCH * L2N * C2];     // ~31.5 MB (L2-resident)
__device__ float g_part[NTG * BATCH * AD];           // partials, every slot written each launch
__device__ unsigned int g_ctr;                       // work counter (reset by k_front)

// ---- f32x2 packed helpers -------------------------------------------------
__device__ __forceinline__ ull ffma2(ull a, ull b, ull c) {
    ull d;
    asm("fma.rn.f32x2 %0, %1, %2, %3;" : "=l"(d) : "l"(a), "l"(b), "l"(c));
    return d;
}
__device__ __forceinline__ ull pack2(float lo, float hi) {
    ull d;
    asm("mov.b64 %0, {%1, %2};" : "=l"(d) : "f"(lo), "f"(hi));
    return d;
}
__device__ __forceinline__ void unpack2(ull v, float& lo, float& hi) {
    asm("mov.b64 {%0, %1}, %2;" : "=f"(lo), "=f"(hi) : "l"(v));
}

// ---------------------------------------------------------------------------
// Kernel 1: blocks 1+2. grid (64, 2), block 256. Also resets work counter.
// ---------------------------------------------------------------------------
__global__ __launch_bounds__(256) void k_front(
    const float* __restrict__ state, const float* __restrict__ k1,
    const float* __restrict__ b1, const float* __restrict__ k2,
    const float* __restrict__ b2)
{
    if (blockIdx.x == 0 && blockIdx.y == 0 && threadIdx.x == 0) g_ctr = 0u;

    __shared__ float s_y1[64 * C1];   // 32 KB
    const int b   = blockIdx.x;
    const int ty  = blockIdx.y;
    const int tid = threadIdx.x;
    const int t0  = ty * 60;
    const float* st = state + (size_t)b * L0 * C0;

    // ---- y1 rows t0..t0+63 ----
    {
        const int c1 = tid & (C1 - 1);
        const int g1 = c1 >> 3;
        float kr[KW];
        const float bb = b1[c1];
        #pragma unroll
        for (int k = 0; k < KW; k++) kr[k] = k1[k * C1 + c1];
        for (int i = (tid >> 7); i < 64; i += 2) {
            const int t = t0 + i;
            float z = bb;
            #pragma unroll
            for (int k = 0; k < KW; k++)
                z = fmaf(st[(t + k) * C0 + g1], kr[k], z);
            s_y1[i * C1 + c1] = fmaxf(z, 0.f);
        }
    }
    __syncthreads();

    // ---- y2 rows t0..t0+59 ----
    for (int q = 0; q < 4; q++) {
        const int c2 = tid + q * 256;
        const int g2 = c2 >> 3;
        float kr[KW];
        const float bb = b2[c2];
        #pragma unroll
        for (int k = 0; k < KW; k++) kr[k] = k2[k * C2 + c2];
        float* yout = g_y2 + ((size_t)b * L2N + t0) * C2 + c2;
        for (int i = 0; i < 60; i++) {
            float z = bb;
            #pragma unroll
            for (int k = 0; k < KW; k++)
                z = fmaf(s_y1[(i + k) * C1 + g2], kr[k], z);
            yout[(size_t)i * C2] = fmaxf(z, 0.f);
        }
    }
}

// ---------------------------------------------------------------------------
// Kernel 2: fused block3 + dense, persistent, dynamic work list, FFMA2 packed
// over filter pairs. grid 148, block 256.
// ---------------------------------------------------------------------------
__global__ __launch_bounds__(256, 1) void k_back(
    const float* __restrict__ k3, const float* __restrict__ b3,
    const float* __restrict__ W)
{
    __shared__ float s_part[8][BPC][AD];   // per-warp, per-batch partials
    __shared__ int s_item;
    const int tid  = threadIdx.x;
    const int lane = tid & 31;
    const int wid  = tid >> 5;

    for (;;) {
        if (tid == 0) s_item = (int)atomicAdd(&g_ctr, 1u);
        __syncthreads();
        const int item = s_item;
        if (item >= NITEMS) break;

        const int tg    = item / NBCH;
        const int bchnk = item % NBCH;
        const int tblk  = tg % NTBLK;
        const int gblk  = tg / NTBLK;
        const int t30   = tblk * TT;
        const int g3    = gblk * 256 + tid;
        const int c3b   = g3 * 8;
        const int b0    = bchnk * BPC;

        // ---- weights: packed filter pairs (consecutive floats = packed) ----
        ull kr2[KW][4];
        #pragma unroll
        for (int k = 0; k < KW; k++) {
            const ull* p = (const ull*)(k3 + k * C3 + c3b);
            #pragma unroll
            for (int fp = 0; fp < 4; fp++) kr2[k][fp] = p[fp];
        }
        ull br2[4];
        {
            const ull* p = (const ull*)(b3 + c3b);
            #pragma unroll
            for (int fp = 0; fp < 4; fp++) br2[fp] = p[fp];
        }
        // W[(t,c),a]: pack (W[c][a], W[c+1][a]) per action
        ull wr2[TT][4][AD];
        #pragma unroll
        for (int i = 0; i < TT; i++) {
            const float* wp = W + ((size_t)(t30 + i) * C3 + c3b) * AD;
            #pragma unroll
            for (int fp = 0; fp < 4; fp++) {
                float4 q = *(const float4*)(wp + fp * 4);
                wr2[i][fp][0] = pack2(q.x, q.z);
                wr2[i][fp][1] = pack2(q.y, q.w);
            }
        }

        // ---- batch loop with one-batch-ahead prefetch ----
        const float* ybase = g_y2 + ((size_t)b0 * L2N + t30) * C2 + g3;
        float yv[TT + 4];
        #pragma unroll
        for (int j = 0; j < TT + 4; j++) yv[j] = ybase[(size_t)j * C2];

        for (int bb = 0; bb < BPC; bb++) {
            float yn[TT + 4];
            if (bb + 1 < BPC) {
                const float* yp = ybase + (size_t)(bb + 1) * L2N * C2;
                #pragma unroll
                for (int j = 0; j < TT + 4; j++) yn[j] = yp[(size_t)j * C2];
            }
            ull yv2[TT + 4];
            #pragma unroll
            for (int j = 0; j < TT + 4; j++) yv2[j] = pack2(yv[j], yv[j]);

            ull a0p = 0ull, a1p = 0ull;   // packed accumulators (both = +0.0f pair)
            #pragma unroll
            for (int i = 0; i < TT; i++) {
                #pragma unroll
                for (int fp = 0; fp < 4; fp++) {
                    ull z2 = br2[fp];
                    #pragma unroll
                    for (int k = 0; k < KW; k++)
                        z2 = ffma2(yv2[i + k], kr2[k][fp], z2);
                    float v0, v1;
                    unpack2(z2, v0, v1);
                    v0 = fmaxf(v0, 0.f);
                    v1 = fmaxf(v1, 0.f);
                    const ull v2 = pack2(v0, v1);
                    a0p = ffma2(v2, wr2[i][fp][0], a0p);
                    a1p = ffma2(v2, wr2[i][fp][1], a1p);
                }
            }
            // horizontal add, then warp reduce
            float a0l, a0h, a1l, a1h;
            unpack2(a0p, a0l, a0h);
            unpack2(a1p, a1l, a1h);
            float a0 = a0l + a0h, a1 = a1l + a1h;
            #pragma unroll
            for (int off = 16; off; off >>= 1) {
                a0 += __shfl_xor_sync(0xffffffffu, a0, off);
                a1 += __shfl_xor_sync(0xffffffffu, a1, off);
            }
            if (lane == 0) {
                s_part[wid][bb][0] = a0;
                s_part[wid][bb][1] = a1;
            }
            #pragma unroll
            for (int j = 0; j < TT + 4; j++) yv[j] = yn[j];
        }
        __syncthreads();
        if (tid < BPC * AD) {
            const int bb = tid >> 1, a = tid & 1;
            float s = 0.f;
            #pragma unroll
            for (int w = 0; w < 8; w++) s += s_part[w][bb][a];
            g_part[tg * (BATCH * AD) + (b0 + bb) * AD + a] = s;
        }
        __syncthreads();
    }
}

// ---------------------------------------------------------------------------
// Kernel 3: reduce partials over 116 tg tiles, bias + tanh.
// ---------------------------------------------------------------------------
__global__ void k_out(const float* __restrict__ bd, float* __restrict__ out) {
    const int i = threadIdx.x;   // 128 = BATCH*AD
    float s = 0.f;
    for (int tg = 0; tg < NTG; tg++) s += g_part[tg * (BATCH * AD) + i];
    out[i] = tanhf(s + bd[i & 1]);
}

extern "C" void kernel_launch(void* const* d_in, const int* in_sizes, int n_in,
                              void* d_out, int out_size) {
    (void)in_sizes; (void)n_in; (void)out_size;
    const float* state = (const float*)d_in[0];
    const float* k1    = (const float*)d_in[1];
    const float* b1    = (const float*)d_in[2];
    const float* k2    = (const float*)d_in[3];
    const float* b2    = (const float*)d_in[4];
    const float* k3    = (const float*)d_in[5];
    const float* b3    = (const float*)d_in[6];
    const float* W     = (const float*)d_in[7];
    const float* bd    = (const float*)d_in[8];
    float* out = (float*)d_out;

    k_front<<<dim3(BATCH, 2), 256>>>(state, k1, b1, k2, b2);
    k_back <<<GRID_BACK, 256>>>(k3, b3, W);
    k_out  <<<1, 128>>>(bd, out);
}

// round 4
// speedup vs baseline: 1.3015x; 1.0366x over previous
#include <cuda_runtime.h>
#include <math.h>

typedef unsigned long long ull;

// Problem constants
#define BATCH 64
#define L0 128
#define C0 16
#define KW 5
#define C1 128
#define C2 1024
#define L2N 120
#define C3 8192
#define L3 116
#define AD 2

// k_back decomposition: unit = (tblk, g32) owned by ONE warp (32 lanes = 32 groups)
#define TT 4
#define NTBLK (L3 / TT)        // 29
#define NG32 (C2 / 32)         // 32
#define NU (NTBLK * NG32)      // 928 units
#define BPT 8                  // batches per task
#define NBC (BATCH / BPT)      // 8
#define NTASK (NU * NBC)       // 7424 tasks
#define GRID_BACK 148
#define NWARPS (GRID_BACK * 8) // 1184
#define TPW (NTASK / NWARPS)   // 6
#define TREM (NTASK % NWARPS)  // 320

// Scratch (device globals; no allocation)
__device__ float g_y2[(size_t)BATCH * L2N * C2];   // ~31.5 MB (L2-resident)
__device__ float g_part[NU * BATCH * AD];          // per-unit partials (every slot written)

// ---- f32x2 packed helpers -------------------------------------------------
__device__ __forceinline__ ull ffma2(ull a, ull b, ull c) {
    ull d;
    asm("fma.rn.f32x2 %0, %1, %2, %3;" : "=l"(d) : "l"(a), "l"(b), "l"(c));
    return d;
}
__device__ __forceinline__ ull add2(ull a, ull b) {
    ull d;
    asm("add.rn.f32x2 %0, %1, %2;" : "=l"(d) : "l"(a), "l"(b));
    return d;
}
__device__ __forceinline__ ull pack2(float lo, float hi) {
    ull d;
    asm("mov.b64 %0, {%1, %2};" : "=l"(d) : "f"(lo), "f"(hi));
    return d;
}
__device__ __forceinline__ void unpack2(ull v, float& lo, float& hi) {
    asm("mov.b64 {%0, %1}, %2;" : "=f"(lo), "=f"(hi) : "l"(v));
}

// ---------------------------------------------------------------------------
// Kernel 1: blocks 1+2. grid (64, 4), block 256. Sliding-window y2 conv.
// ---------------------------------------------------------------------------
__global__ __launch_bounds__(256) void k_front(
    const float* __restrict__ state, const float* __restrict__ k1,
    const float* __restrict__ b1, const float* __restrict__ k2,
    const float* __restrict__ b2)
{
    __shared__ float s_y1[34 * C1];   // y1 local rows [0,34) -> global t0+i  (17.4 KB)
    const int b   = blockIdx.x;
    const int ty  = blockIdx.y;
    const int tid = threadIdx.x;
    const int t0  = ty * 30;          // this CTA emits y2 rows [t0, t0+30)
    const float* st = state + (size_t)b * L0 * C0;

    // ---- y1 rows t0..t0+33 ----
    {
        const int c1 = tid & (C1 - 1);
        const int g1 = c1 >> 3;
        float kr[KW];
        const float bb = b1[c1];
        #pragma unroll
        for (int k = 0; k < KW; k++) kr[k] = k1[k * C1 + c1];
        for (int i = (tid >> 7); i < 34; i += 2) {
            const int t = t0 + i;
            float z = bb;
            #pragma unroll
            for (int k = 0; k < KW; k++)
                z = fmaf(st[(t + k) * C0 + g1], kr[k], z);
            s_y1[i * C1 + c1] = fmaxf(z, 0.f);
        }
    }
    __syncthreads();

    // ---- y2 rows t0..t0+29, sliding window (1 LDS per output) ----
    #pragma unroll
    for (int q = 0; q < 4; q++) {
        const int c2 = tid + q * 256;
        const int g2 = c2 >> 3;
        float kr[KW];
        const float bb = b2[c2];
        #pragma unroll
        for (int k = 0; k < KW; k++) kr[k] = k2[k * C2 + c2];
        float* yout = g_y2 + ((size_t)b * L2N + t0) * C2 + c2;
        float w0 = s_y1[0 * C1 + g2];
        float w1 = s_y1[1 * C1 + g2];
        float w2 = s_y1[2 * C1 + g2];
        float w3 = s_y1[3 * C1 + g2];
        #pragma unroll 5
        for (int i = 0; i < 30; i++) {
            const float w4 = s_y1[(i + 4) * C1 + g2];
            float z = bb;
            z = fmaf(w0, kr[0], z);
            z = fmaf(w1, kr[1], z);
            z = fmaf(w2, kr[2], z);
            z = fmaf(w3, kr[3], z);
            z = fmaf(w4, kr[4], z);
            yout[(size_t)i * C2] = fmaxf(z, 0.f);
            w0 = w1; w1 = w2; w2 = w3; w3 = w4;
        }
    }
}

// ---------------------------------------------------------------------------
// Kernel 2: fused block3 + dense. Warp-autonomous static schedule:
// no smem, no syncthreads, no atomics. grid 148, block 256.
// ---------------------------------------------------------------------------
__global__ __launch_bounds__(256) void k_back(
    const float* __restrict__ k3, const float* __restrict__ b3,
    const float* __restrict__ W)
{
    const int tid  = threadIdx.x;
    const int lane = tid & 31;
    const int wid  = tid >> 5;
    const int wg   = blockIdx.x * 8 + wid;

    const int cnt   = TPW + (wg < TREM);
    const int start = wg * TPW + (wg < TREM ? wg : TREM);
    const int end   = start + cnt;

    int uprev = -1;
    ull kr2[KW][4];
    ull br2[4];
    ull wr2[TT][4][AD];

    // initial row prefetch for first task
    float yv[TT + 4];
    {
        const int j = start, u = j >> 3, bc = j & 7;
        const int tblk = u % NTBLK, g32 = u / NTBLK;
        const float* p = g_y2 + ((size_t)(bc * BPT) * L2N + tblk * TT) * C2
                       + (g32 * 32 + lane);
        #pragma unroll
        for (int r = 0; r < TT + 4; r++) yv[r] = p[(size_t)r * C2];
    }

    for (int j = start; j < end; j++) {
        const int u    = j >> 3, bc = j & 7;
        const int tblk = u % NTBLK, g32 = u / NTBLK;
        const int g3   = g32 * 32 + lane;
        const int t30  = tblk * TT;

        if (u != uprev) {   // <=2 weight loads per warp for the whole kernel
            uprev = u;
            const int c3b = g3 * 8;
            #pragma unroll
            for (int k = 0; k < KW; k++) {
                const ull* p = (const ull*)(k3 + k * C3 + c3b);
                #pragma unroll
                for (int fp = 0; fp < 4; fp++) kr2[k][fp] = p[fp];
            }
            {
                const ull* p = (const ull*)(b3 + c3b);
                #pragma unroll
                for (int fp = 0; fp < 4; fp++) br2[fp] = p[fp];
            }
            #pragma unroll
            for (int i = 0; i < TT; i++) {
                const float* wp = W + ((size_t)(t30 + i) * C3 + c3b) * AD;
                #pragma unroll
                for (int fp = 0; fp < 4; fp++) {
                    float4 q = *(const float4*)(wp + fp * 4);
                    wr2[i][fp][0] = pack2(q.x, q.z);   // action 0, filters (2fp, 2fp+1)
                    wr2[i][fp][1] = pack2(q.y, q.w);   // action 1
                }
            }
        }

        const float* ytask = g_y2 + ((size_t)(bc * BPT) * L2N + t30) * C2 + g3;
        float* gout = g_part + ((size_t)u * BATCH + bc * BPT) * AD;

        for (int bb = 0; bb < BPT; bb++) {
            // ---- prefetch next batch (crosses task boundary) ----
            float yn[TT + 4];
            const float* pn = (const float*)0;
            if (bb + 1 < BPT) {
                pn = ytask + (size_t)(bb + 1) * L2N * C2;
            } else if (j + 1 < end) {
                const int j2 = j + 1, u2 = j2 >> 3, bc2 = j2 & 7;
                const int tb2 = u2 % NTBLK, gg2 = u2 / NTBLK;
                pn = g_y2 + ((size_t)(bc2 * BPT) * L2N + tb2 * TT) * C2
                   + (gg2 * 32 + lane);
            }
            if (pn) {
                #pragma unroll
                for (int r = 0; r < TT + 4; r++) yn[r] = pn[(size_t)r * C2];
            }

            // ---- conv + relu + dense, packed over filter pairs ----
            ull yv2[TT + 4];
            #pragma unroll
            for (int r = 0; r < TT + 4; r++) yv2[r] = pack2(yv[r], yv[r]);

            ull a0p = 0ull, a1p = 0ull;
            #pragma unroll
            for (int i = 0; i < TT; i++) {
                #pragma unroll
                for (int fp = 0; fp < 4; fp++) {
                    ull z2 = br2[fp];
                    #pragma unroll
                    for (int k = 0; k < KW; k++)
                        z2 = ffma2(yv2[i + k], kr2[k][fp], z2);
                    float v0, v1;
                    unpack2(z2, v0, v1);
                    v0 = fmaxf(v0, 0.f);
                    v1 = fmaxf(v1, 0.f);
                    const ull v2 = pack2(v0, v1);
                    a0p = ffma2(v2, wr2[i][fp][0], a0p);
                    a1p = ffma2(v2, wr2[i][fp][1], a1p);
                }
            }

            // ---- reduce: fold to one packed (act0, act1), 5-step packed shfl ----
            float a0l, a0h, a1l, a1h;
            unpack2(a0p, a0l, a0h);
            unpack2(a1p, a1l, a1h);
            ull c = pack2(a0l + a0h, a1l + a1h);
            #pragma unroll
            for (int off = 16; off; off >>= 1)
                c = add2(c, __shfl_xor_sync(0xffffffffu, c, off));
            if (lane == 0) {
                float r0, r1;
                unpack2(c, r0, r1);
                float2 res; res.x = r0; res.y = r1;
                *(float2*)(gout + bb * AD) = res;
            }

            #pragma unroll
            for (int r = 0; r < TT + 4; r++) yv[r] = yn[r];
        }
    }
}

// ---------------------------------------------------------------------------
// Kernel 3: reduce 928 partials per output, bias + tanh. grid 128, block 256.
// ---------------------------------------------------------------------------
__global__ __launch_bounds__(256) void k_out(
    const float* __restrict__ bd, float* __restrict__ out)
{
    __shared__ float s[8];
    const int i   = blockIdx.x;        // output index (b*AD + a), 0..127
    const int tid = threadIdx.x;
    float v = 0.f;
    for (int u = tid; u < NU; u += 256)
        v += g_part[(size_t)u * (BATCH * AD) + i];
    #pragma unroll
    for (int off = 16; off; off >>= 1)
        v += __shfl_xor_sync(0xffffffffu, v, off);
    if ((tid & 31) == 0) s[tid >> 5] = v;
    __syncthreads();
    if (tid == 0) {
        float sum = 0.f;
        #pragma unroll
        for (int w = 0; w < 8; w++) sum += s[w];
        out[i] = tanhf(sum + bd[i & 1]);
    }
}

extern "C" void kernel_launch(void* const* d_in, const int* in_sizes, int n_in,
                              void* d_out, int out_size) {
    (void)in_sizes; (void)n_in; (void)out_size;
    const float* state = (const float*)d_in[0];
    const float* k1    = (const float*)d_in[1];
    const float* b1    = (const float*)d_in[2];
    const float* k2    = (const float*)d_in[3];
    const float* b2    = (const float*)d_in[4];
    const float* k3    = (const float*)d_in[5];
    const float* b3    = (const float*)d_in[6];
    const float* W     = (const float*)d_in[7];
    const float* bd    = (const float*)d_in[8];
    float* out = (float*)d_out;

    k_front<<<dim3(BATCH, 4), 256>>>(state, k1, b1, k2, b2);
    k_back <<<GRID_BACK, 256>>>(k3, b3, W);
    k_out  <<<128, 256>>>(bd, out);
}

// round 6
// speedup vs baseline: 1.4111x; 1.0842x over previous
#include <cuda_runtime.h>
#include <math.h>

typedef unsigned long long ull;

// Problem constants
#define BATCH 64
#define L0 128
#define C0 16
#define KW 5
#define C1 128
#define C2 1024
#define L2N 120
#define C3 8192
#define L3 116
#define AD 2

// k_back decomposition: unit = (tblk, g8) owned by ONE warp.
// lane = (group-local gl = lane>>2 in [0,8), filter-pair fp = lane&3)
#define TT 4
#define NTBLK (L3 / TT)          // 29
#define NG8 (C2 / 8)             // 128
#define NU (NTBLK * NG8)         // 3712 units
#define BPT 8                    // batches per task
#define NTASK (NU * (BATCH/BPT)) // 29696
#define GRID_BACK 296            // 2 CTAs/SM resident
#define NWARPS (GRID_BACK * 8)   // 2368
#define TPW (NTASK / NWARPS)     // 12
#define TREM (NTASK % NWARPS)    // 1280

// Scratch (device globals; no allocation)
__device__ float g_y2[(size_t)BATCH * L2N * C2];   // ~31.5 MB (L2-resident)
__device__ float g_part[(size_t)NU * BATCH * AD];  // 1.9 MB partials

// ---- f32x2 packed helpers -------------------------------------------------
__device__ __forceinline__ ull ffma2(ull a, ull b, ull c) {
    ull d;
    asm("fma.rn.f32x2 %0, %1, %2, %3;" : "=l"(d) : "l"(a), "l"(b), "l"(c));
    return d;
}
__device__ __forceinline__ ull add2(ull a, ull b) {
    ull d;
    asm("add.rn.f32x2 %0, %1, %2;" : "=l"(d) : "l"(a), "l"(b));
    return d;
}
__device__ __forceinline__ ull pack2(float lo, float hi) {
    ull d;
    asm("mov.b64 %0, {%1, %2};" : "=l"(d) : "f"(lo), "f"(hi));
    return d;
}
__device__ __forceinline__ void unpack2(ull v, float& lo, float& hi) {
    asm("mov.b64 {%0, %1}, %2;" : "=f"(lo), "=f"(hi) : "l"(v));
}

// ---------------------------------------------------------------------------
// Kernel 1: blocks 1+2. grid (64, 8), block 256. 15 y2 rows per CTA.
// ---------------------------------------------------------------------------
__global__ __launch_bounds__(256) void k_front(
    const float* __restrict__ state, const float* __restrict__ k1,
    const float* __restrict__ b1, const float* __restrict__ k2,
    const float* __restrict__ b2)
{
    __shared__ float s_y1[19 * C1];   // 9.5 KB
    const int b   = blockIdx.x;
    const int ty  = blockIdx.y;
    const int tid = threadIdx.x;
    const int t0  = ty * 15;          // y2 rows [t0, t0+15)
    const float* st = state + (size_t)b * L0 * C0;

    // ---- y1 rows t0..t0+18 ----
    {
        const int c1 = tid & (C1 - 1);
        const int g1 = c1 >> 3;
        float kr[KW];
        const float bb = b1[c1];
        #pragma unroll
        for (int k = 0; k < KW; k++) kr[k] = k1[k * C1 + c1];
        for (int i = (tid >> 7); i < 19; i += 2) {
            const int t = t0 + i;
            float z = bb;
            #pragma unroll
            for (int k = 0; k < KW; k++)
                z = fmaf(st[(t + k) * C0 + g1], kr[k], z);
            s_y1[i * C1 + c1] = fmaxf(z, 0.f);
        }
    }
    __syncthreads();

    // ---- y2 rows t0..t0+14, sliding window ----
    #pragma unroll
    for (int q = 0; q < 4; q++) {
        const int c2 = tid + q * 256;
        const int g2 = c2 >> 3;
        float kr[KW];
        const float bb = b2[c2];
        #pragma unroll
        for (int k = 0; k < KW; k++) kr[k] = k2[k * C2 + c2];
        float* yout = g_y2 + ((size_t)b * L2N + t0) * C2 + c2;
        float w0 = s_y1[0 * C1 + g2];
        float w1 = s_y1[1 * C1 + g2];
        float w2 = s_y1[2 * C1 + g2];
        float w3 = s_y1[3 * C1 + g2];
        #pragma unroll
        for (int i = 0; i < 15; i++) {
            const float w4 = s_y1[(i + 4) * C1 + g2];
            float z = bb;
            z = fmaf(w0, kr[0], z);
            z = fmaf(w1, kr[1], z);
            z = fmaf(w2, kr[2], z);
            z = fmaf(w3, kr[3], z);
            z = fmaf(w4, kr[4], z);
            yout[(size_t)i * C2] = fmaxf(z, 0.f);
            w0 = w1; w1 = w2; w2 = w3; w3 = w4;
        }
    }
}

// ---------------------------------------------------------------------------
// Kernel 2: fused block3 + dense. One filter-pair per lane (low regs),
// deferred interleaved warp reduction. grid 296, block 256.
// ---------------------------------------------------------------------------
__global__ __launch_bounds__(256, 2) void k_back(
    const float* __restrict__ k3, const float* __restrict__ b3,
    const float* __restrict__ W)
{
    const int tid  = threadIdx.x;
    const int lane = tid & 31;
    const int wid  = tid >> 5;
    const int wg   = blockIdx.x * 8 + wid;

    const int cnt   = TPW + (wg < TREM);
    const int start = wg * TPW + (wg < TREM ? wg : TREM);
    const int end   = start + cnt;

    const int fp = lane & 3;     // filter pair within group
    const int gl = lane >> 2;    // group within g8 block

    int uprev = -1;
    ull kr2[KW];       // conv weights, packed filter pair
    ull br2;           // bias pair
    ull wr2[TT][AD];   // dense weights: (w[c][a], w[c+1][a]) per t

    // initial row prefetch for first task
    float yv[TT + 4];
    {
        const int j = start, u = j >> 3, bc = j & 7;
        const int tblk = u % NTBLK, g8 = u / NTBLK;
        const float* p = g_y2 + ((size_t)(bc * BPT) * L2N + tblk * TT) * C2
                       + (g8 * 8 + gl);
        #pragma unroll
        for (int r = 0; r < TT + 4; r++) yv[r] = p[(size_t)r * C2];
    }

    for (int j = start; j < end; j++) {
        const int u    = j >> 3, bc = j & 7;
        const int tblk = u % NTBLK, g8 = u / NTBLK;
        const int g3   = g8 * 8 + gl;
        const int t30  = tblk * TT;
        const int c    = g3 * 8 + fp * 2;   // first of 2 channels this lane owns

        if (u != uprev) {
            uprev = u;
            #pragma unroll
            for (int k = 0; k < KW; k++)
                kr2[k] = *(const ull*)(k3 + k * C3 + c);
            br2 = *(const ull*)(b3 + c);
            #pragma unroll
            for (int i = 0; i < TT; i++) {
                float4 q = *(const float4*)(W + ((size_t)(t30 + i) * C3 + c) * AD);
                wr2[i][0] = pack2(q.x, q.z);   // action 0: (w[c], w[c+1])
                wr2[i][1] = pack2(q.y, q.w);   // action 1
            }
        }

        const float* ytask = g_y2 + ((size_t)(bc * BPT) * L2N + t30) * C2 + g3;
        ull acc[BPT];

        for (int bb = 0; bb < BPT; bb++) {
            // ---- prefetch next batch (crosses task boundary) ----
            float yn[TT + 4];
            const float* pn = (const float*)0;
            if (bb + 1 < BPT) {
                pn = ytask + (size_t)(bb + 1) * L2N * C2;
            } else if (j + 1 < end) {
                const int j2 = j + 1, u2 = j2 >> 3, bc2 = j2 & 7;
                const int tb2 = u2 % NTBLK, gg2 = u2 / NTBLK;
                pn = g_y2 + ((size_t)(bc2 * BPT) * L2N + tb2 * TT) * C2
                   + (gg2 * 8 + gl);
            }
            if (pn) {
                #pragma unroll
                for (int r = 0; r < TT + 4; r++) yn[r] = pn[(size_t)r * C2];
            }

            ull yv2[TT + 4];
            #pragma unroll
            for (int r = 0; r < TT + 4; r++) yv2[r] = pack2(yv[r], yv[r]);

            ull a0p = 0ull, a1p = 0ull;
            #pragma unroll
            for (int i = 0; i < TT; i++) {
                ull z2 = br2;
                #pragma unroll
                for (int k = 0; k < KW; k++)
                    z2 = ffma2(yv2[i + k], kr2[k], z2);
                float v0, v1;
                unpack2(z2, v0, v1);
                v0 = fmaxf(v0, 0.f);
                v1 = fmaxf(v1, 0.f);
                const ull v2 = pack2(v0, v1);
                a0p = ffma2(v2, wr2[i][0], a0p);
                a1p = ffma2(v2, wr2[i][1], a1p);
            }
            // fold filter-pair halves -> packed (act0, act1)
            float a0l, a0h, a1l, a1h;
            unpack2(a0p, a0l, a0h);
            unpack2(a1p, a1l, a1h);
            acc[bb] = pack2(a0l + a0h, a1l + a1h);

            #pragma unroll
            for (int r = 0; r < TT + 4; r++) yv[r] = yn[r];
        }

        // ---- deferred warp reduction: 8 interleaved chains ----
        #pragma unroll
        for (int off = 16; off; off >>= 1) {
            #pragma unroll
            for (int bb = 0; bb < BPT; bb++)
                acc[bb] = add2(acc[bb], __shfl_xor_sync(0xffffffffu, acc[bb], off));
        }
        if (lane == 0) {
            float* gout = g_part + ((size_t)u * BATCH + bc * BPT) * AD; // 16 floats
            #pragma unroll
            for (int q = 0; q < 4; q++) {
                float x0, x1, x2, x3;
                unpack2(acc[2 * q],     x0, x1);
                unpack2(acc[2 * q + 1], x2, x3);
                float4 v; v.x = x0; v.y = x1; v.z = x2; v.w = x3;
                *(float4*)(gout + q * 4) = v;
            }
        }
    }
}

// ---------------------------------------------------------------------------
// Kernel 3: reduce 3712 partials per output, bias + tanh. grid 128, block 256.
// ---------------------------------------------------------------------------
__global__ __launch_bounds__(256) void k_out(
    const float* __restrict__ bd, float* __restrict__ out)
{
    __shared__ float s[8];
    const int i   = blockIdx.x;        // output index (b*AD + a)
    const int tid = threadIdx.x;
    float v = 0.f;
    for (int u = tid; u < NU; u += 256)
        v += g_part[(size_t)u * (BATCH * AD) + i];
    #pragma unroll
    for (int off = 16; off; off >>= 1)
        v += __shfl_xor_sync(0xffffffffu, v, off);
    if ((tid & 31) == 0) s[tid >> 5] = v;
    __syncthreads();
    if (tid == 0) {
        float sum = 0.f;
        #pragma unroll
        for (int w = 0; w < 8; w++) sum += s[w];
        out[i] = tanhf(sum + bd[i & 1]);
    }
}

extern "C" void kernel_launch(void* const* d_in, const int* in_sizes, int n_in,
                              void* d_out, int out_size) {
    (void)in_sizes; (void)n_in; (void)out_size;
    const float* state = (const float*)d_in[0];
    const float* k1    = (const float*)d_in[1];
    const float* b1    = (const float*)d_in[2];
    const float* k2    = (const float*)d_in[3];
    const float* b2    = (const float*)d_in[4];
    const float* k3    = (const float*)d_in[5];
    const float* b3    = (const float*)d_in[6];
    const float* W     = (const float*)d_in[7];
    const float* bd    = (const float*)d_in[8];
    float* out = (float*)d_out;

    k_front<<<dim3(BATCH, 8), 256>>>(state, k1, b1, k2, b2);
    k_back <<<GRID_BACK, 256>>>(k3, b3, W);
    k_out  <<<128, 256>>>(bd, out);
}

// round 7
// speedup vs baseline: 1.5143x; 1.0731x over previous
#include <cuda_runtime.h>
#include <math.h>

typedef unsigned long long ull;

// Problem constants
#define BATCH 64
#define L0 128
#define C0 16
#define KW 5
#define C1 128
#define C2 1024
#define L2N 120
#define C3 8192
#define L3 116
#define AD 2

// k_back decomposition: unit = (tblk, g8) owned by ONE warp.
// lane = (group-local gl = lane>>2 in [0,8), filter-pair fp = lane&3)
#define TT 4
#define NTBLK (L3 / TT)          // 29
#define NG8 (C2 / 8)             // 128
#define NU (NTBLK * NG8)         // 3712 units
#define BPT 8                    // batches per task
#define NTASK (NU * (BATCH/BPT)) // 29696
#define GRID_BACK 444            // 3 CTAs/SM resident
#define NWARPS (GRID_BACK * 8)   // 3552
#define TPW (NTASK / NWARPS)     // 8
#define TREM (NTASK % NWARPS)    // 1280

// k_front tiling
#define FROWS 8                  // y2 rows per CTA
#define FY1 (FROWS + KW - 1)     // 12 y1 rows

// Scratch (device globals; no allocation)
__device__ float g_y2[(size_t)BATCH * L2N * C2];        // ~31.5 MB (L2-resident)
__device__ float g_part2[(size_t)BATCH * NU * 8 * AD];  // 15.2 MB partials

// ---- f32x2 packed helpers -------------------------------------------------
__device__ __forceinline__ ull ffma2(ull a, ull b, ull c) {
    ull d;
    asm("fma.rn.f32x2 %0, %1, %2, %3;" : "=l"(d) : "l"(a), "l"(b), "l"(c));
    return d;
}
__device__ __forceinline__ ull add2(ull a, ull b) {
    ull d;
    asm("add.rn.f32x2 %0, %1, %2;" : "=l"(d) : "l"(a), "l"(b));
    return d;
}
__device__ __forceinline__ ull pack2(float lo, float hi) {
    ull d;
    asm("mov.b64 %0, {%1, %2};" : "=l"(d) : "f"(lo), "f"(hi));
    return d;
}
__device__ __forceinline__ void unpack2(ull v, float& lo, float& hi) {
    asm("mov.b64 {%0, %1}, %2;" : "=f"(lo), "=f"(hi) : "l"(v));
}

// ---------------------------------------------------------------------------
// Kernel 1: blocks 1+2. grid (64, 15), block 256. 8 y2 rows per CTA.
// ---------------------------------------------------------------------------
__global__ __launch_bounds__(256) void k_front(
    const float* __restrict__ state, const float* __restrict__ k1,
    const float* __restrict__ b1, const float* __restrict__ k2,
    const float* __restrict__ b2)
{
    __shared__ float s_y1[FY1 * C1];   // 6 KB
    const int b   = blockIdx.x;
    const int ty  = blockIdx.y;
    const int tid = threadIdx.x;
    const int t0  = ty * FROWS;        // y2 rows [t0, t0+8)
    const float* st = state + (size_t)b * L0 * C0;

    // ---- y1 rows t0..t0+11 ----
    {
        const int c1 = tid & (C1 - 1);
        const int g1 = c1 >> 3;
        float kr[KW];
        const float bb = b1[c1];
        #pragma unroll
        for (int k = 0; k < KW; k++) kr[k] = k1[k * C1 + c1];
        #pragma unroll
        for (int i = (tid >> 7); i < FY1; i += 2) {
            const int t = t0 + i;
            float z = bb;
            #pragma unroll
            for (int k = 0; k < KW; k++)
                z = fmaf(st[(t + k) * C0 + g1], kr[k], z);
            s_y1[i * C1 + c1] = fmaxf(z, 0.f);
        }
    }
    __syncthreads();

    // ---- y2 rows t0..t0+7, sliding window ----
    #pragma unroll
    for (int q = 0; q < 4; q++) {
        const int c2 = tid + q * 256;
        const int g2 = c2 >> 3;
        float kr[KW];
        const float bb = b2[c2];
        #pragma unroll
        for (int k = 0; k < KW; k++) kr[k] = k2[k * C2 + c2];
        float* yout = g_y2 + ((size_t)b * L2N + t0) * C2 + c2;
        float w0 = s_y1[0 * C1 + g2];
        float w1 = s_y1[1 * C1 + g2];
        float w2 = s_y1[2 * C1 + g2];
        float w3 = s_y1[3 * C1 + g2];
        #pragma unroll
        for (int i = 0; i < FROWS; i++) {
            const float w4 = s_y1[(i + 4) * C1 + g2];
            float z = bb;
            z = fmaf(w0, kr[0], z);
            z = fmaf(w1, kr[1], z);
            z = fmaf(w2, kr[2], z);
            z = fmaf(w3, kr[3], z);
            z = fmaf(w4, kr[4], z);
            yout[(size_t)i * C2] = fmaxf(z, 0.f);
            w0 = w1; w1 = w2; w2 = w3; w3 = w4;
        }
    }
}

// ---------------------------------------------------------------------------
// Kernel 2: fused block3 + dense. One filter-pair per lane, quad-only
// reduction, 3 CTAs/SM. grid 444, block 256.
// ---------------------------------------------------------------------------
__global__ __launch_bounds__(256, 3) void k_back(
    const float* __restrict__ k3, const float* __restrict__ b3,
    const float* __restrict__ W)
{
    const int tid  = threadIdx.x;
    const int lane = tid & 31;
    const int wid  = tid >> 5;
    const int wg   = blockIdx.x * 8 + wid;

    const int cnt   = TPW + (wg < TREM);
    const int start = wg * TPW + (wg < TREM ? wg : TREM);
    const int end   = start + cnt;

    const int fp = lane & 3;     // filter pair within group
    const int gl = lane >> 2;    // group within g8 block

    int uprev = -1;
    ull kr2[KW];       // conv weights, packed filter pair
    ull br2 = 0;       // bias pair
    ull wr2[TT][AD];   // dense weights

    for (int j = start; j < end; j++) {
        const int u    = j >> 3, bc = j & 7;
        const int tblk = u % NTBLK, g8 = u / NTBLK;
        const int g3   = g8 * 8 + gl;
        const int t30  = tblk * TT;
        const int c    = g3 * 8 + fp * 2;   // first of 2 channels this lane owns

        if (u != uprev) {
            uprev = u;
            #pragma unroll
            for (int k = 0; k < KW; k++)
                kr2[k] = *(const ull*)(k3 + k * C3 + c);
            br2 = *(const ull*)(b3 + c);
            #pragma unroll
            for (int i = 0; i < TT; i++) {
                float4 q = *(const float4*)(W + ((size_t)(t30 + i) * C3 + c) * AD);
                wr2[i][0] = pack2(q.x, q.z);   // action 0: (w[c], w[c+1])
                wr2[i][1] = pack2(q.y, q.w);   // action 1
            }
        }

        const float* ytask = g_y2 + ((size_t)(bc * BPT) * L2N + t30) * C2 + g3;
        ull acc[BPT];

        #pragma unroll
        for (int bb = 0; bb < BPT; bb++) {
            const float* yp = ytask + (size_t)bb * L2N * C2;
            ull yv2[TT + 4];
            #pragma unroll
            for (int r = 0; r < TT + 4; r++) {
                const float y = yp[(size_t)r * C2];
                yv2[r] = pack2(y, y);
            }

            ull a0p = 0ull, a1p = 0ull;
            #pragma unroll
            for (int i = 0; i < TT; i++) {
                ull z2 = br2;
                #pragma unroll
                for (int k = 0; k < KW; k++)
                    z2 = ffma2(yv2[i + k], kr2[k], z2);
                float v0, v1;
                unpack2(z2, v0, v1);
                v0 = fmaxf(v0, 0.f);
                v1 = fmaxf(v1, 0.f);
                const ull v2 = pack2(v0, v1);
                a0p = ffma2(v2, wr2[i][0], a0p);
                a1p = ffma2(v2, wr2[i][1], a1p);
            }
            // fold filter-pair halves -> packed (act0, act1)
            float a0l, a0h, a1l, a1h;
            unpack2(a0p, a0l, a0h);
            unpack2(a1p, a1l, a1h);
            acc[bb] = pack2(a0l + a0h, a1l + a1h);
        }

        // ---- quad-only reduction (2 interleaved shuffle steps) ----
        #pragma unroll
        for (int off = 1; off <= 2; off <<= 1) {
            #pragma unroll
            for (int bb = 0; bb < BPT; bb++)
                acc[bb] = add2(acc[bb], __shfl_xor_sync(0xffffffffu, acc[bb], off));
        }
        if (fp == 0) {
            // g_part2[b][u][gl] : lanes gl=0..7 write 64B contiguous
            #pragma unroll
            for (int bb = 0; bb < BPT; bb++) {
                const int b = bc * BPT + bb;
                float r0, r1;
                unpack2(acc[bb], r0, r1);
                float2 res; res.x = r0; res.y = r1;
                *(float2*)(g_part2 + (((size_t)b * NU + u) * 8 + gl) * AD) = res;
            }
        }
    }
}

// ---------------------------------------------------------------------------
// Kernel 3: per-batch reduce of NU*8 float2 partials, bias + tanh.
// grid 64 (one block per batch), block 256.
// ---------------------------------------------------------------------------
__global__ __launch_bounds__(256) void k_out(
    const float* __restrict__ bd, float* __restrict__ out)
{
    __shared__ float s0[8], s1[8];
    const int b   = blockIdx.x;
    const int tid = threadIdx.x;
    const float2* p = (const float2*)(g_part2 + (size_t)b * NU * 8 * AD);
    float v0 = 0.f, v1 = 0.f;
    for (int i = tid; i < NU * 8; i += 256) {
        float2 q = p[i];
        v0 += q.x; v1 += q.y;
    }
    #pragma unroll
    for (int off = 16; off; off >>= 1) {
        v0 += __shfl_xor_sync(0xffffffffu, v0, off);
        v1 += __shfl_xor_sync(0xffffffffu, v1, off);
    }
    if ((tid & 31) == 0) { s0[tid >> 5] = v0; s1[tid >> 5] = v1; }
    __syncthreads();
    if (tid == 0) {
        float a0 = 0.f, a1 = 0.f;
        #pragma unroll
        for (int w = 0; w < 8; w++) { a0 += s0[w]; a1 += s1[w]; }
        out[b * AD + 0] = tanhf(a0 + bd[0]);
        out[b * AD + 1] = tanhf(a1 + bd[1]);
    }
}

extern "C" void kernel_launch(void* const* d_in, const int* in_sizes, int n_in,
                              void* d_out, int out_size) {
    (void)in_sizes; (void)n_in; (void)out_size;
    const float* state = (const float*)d_in[0];
    const float* k1    = (const float*)d_in[1];
    const float* b1    = (const float*)d_in[2];
    const float* k2    = (const float*)d_in[3];
    const float* b2    = (const float*)d_in[4];
    const float* k3    = (const float*)d_in[5];
    const float* b3    = (const float*)d_in[6];
    const float* W     = (const float*)d_in[7];
    const float* bd    = (const float*)d_in[8];
    float* out = (float*)d_out;

    k_front<<<dim3(BATCH, L2N / FROWS), 256>>>(state, k1, b1, k2, b2);
    k_back <<<GRID_BACK, 256>>>(k3, b3, W);
    k_out  <<<BATCH, 256>>>(bd, out);
}